// round 16
// baseline (speedup 1.0000x reference)
#include <cuda_runtime.h>
#include <cuda_fp16.h>
#include <cstdint>

#define NPTS 8192
#define DIM  128
#define NTILES 2080            // 64*65/2 triangle tiles, 128x128 each
#define SQOFF 256.0f           // positivity offset (> max row norm ~190)

// ---------------- scratch -----------------------------------------------------
static __device__ __half    g_fh[(size_t)NPTS * DIM];      // fp16 features
static __device__ float     g_sq[NPTS];                    // exact fp32 row norms
static __device__ uint32_t  g_top[(size_t)NPTS * 64 * 6];  // per-row 64 slot key lists

// ---------------- helpers ------------------------------------------------------
__device__ __forceinline__ uint32_t smem_u32(const void* p) {
    uint32_t a;
    asm("{ .reg .u64 t; cvta.to.shared.u64 t, %1; cvt.u32.u64 %0, t; }"
        : "=r"(a) : "l"(p));
    return a;
}
__device__ __forceinline__ void cp16(uint32_t dst, const void* src) {
    asm volatile("cp.async.cg.shared.global [%0], [%1], 16;"
                 :: "r"(dst), "l"(src) : "memory");
}
#define CP_COMMIT() asm volatile("cp.async.commit_group;" ::: "memory")
#define CP_WAIT0()  asm volatile("cp.async.wait_group 0;" ::: "memory")

__device__ __forceinline__ void ldsm_x4(uint32_t* r, uint32_t addr) {
    asm volatile("ldmatrix.sync.aligned.m8n8.x4.shared.b16 {%0,%1,%2,%3}, [%4];"
        : "=r"(r[0]), "=r"(r[1]), "=r"(r[2]), "=r"(r[3]) : "r"(addr));
}
__device__ __forceinline__ void mma16816(float* c, const uint32_t* a,
                                         uint32_t b0, uint32_t b1) {
    asm volatile("mma.sync.aligned.m16n8k16.row.col.f32.f16.f16.f32 "
        "{%0,%1,%2,%3}, {%4,%5,%6,%7}, {%8,%9}, {%0,%1,%2,%3};"
        : "+f"(c[0]), "+f"(c[1]), "+f"(c[2]), "+f"(c[3])
        : "r"(a[0]), "r"(a[1]), "r"(a[2]), "r"(a[3]), "r"(b0), "r"(b1));
}

// pack for POSITIVE floats with 7-bit LOCAL index: 25 value bits, single LOP3
__device__ __forceinline__ uint32_t packpos(float v, int idx) {
    return (__float_as_uint(v) & 0xFFFFFF80u) | (uint32_t)idx;
}

// swizzled byte offset inside a tile with 256B rows (16 chunks of 16B)
__device__ __forceinline__ uint32_t swz(int row, int chunk) {
    return (uint32_t)(row * 256 + (((chunk ^ row) & 7) | (chunk & 8)) * 16);
}

// top-6 insert on packed keys, ascending
__device__ __forceinline__ void ins6u(uint32_t k, uint32_t* nb) {
    if (k < nb[5]) {
        nb[5] = k;
        #pragma unroll
        for (int i = 5; i > 0; i--) {
            uint32_t lo = min(nb[i - 1], nb[i]);
            uint32_t hi = max(nb[i - 1], nb[i]);
            nb[i - 1] = lo; nb[i] = hi;
        }
    }
}
__device__ __forceinline__ void ins6u64(uint64_t k, uint64_t* nb) {
    if (k < nb[5]) {
        nb[5] = k;
        #pragma unroll
        for (int i = 5; i > 0; i--) {
            uint64_t lo = (nb[i] < nb[i - 1]) ? nb[i] : nb[i - 1];
            uint64_t hi = (nb[i] < nb[i - 1]) ? nb[i - 1] : nb[i];
            nb[i - 1] = lo; nb[i] = hi;
        }
    }
}

// ---------------- kernel 1: fp16 convert + exact row norms --------------------
__global__ __launch_bounds__(256) void prep_kernel(const float* __restrict__ f) {
    int wid = threadIdx.x >> 5, lane = threadIdx.x & 31;
    int row = blockIdx.x * 8 + wid;
    float4 v = ((const float4*)f)[row * 32 + lane];
    float s = v.x * v.x + v.y * v.y + v.z * v.z + v.w * v.w;
    __half2 h0 = __floats2half2_rn(v.x, v.y);
    __half2 h1 = __floats2half2_rn(v.z, v.w);
    uint2 u;
    u.x = *(uint32_t*)&h0; u.y = *(uint32_t*)&h1;
    *(uint2*)(g_fh + (size_t)row * DIM + lane * 4) = u;
    #pragma unroll
    for (int o = 16; o; o >>= 1) s += __shfl_xor_sync(0xffffffffu, s, o);
    if (lane == 0) g_sq[row] = s;
}

// ---------------- kernel 2: 128x128 symmetric tile, 2 col-half passes ---------
#define SM_A   0                           // 128 x 256 = 32768
#define SM_B   32768                       // 128 x 256 = 32768
#define SM_STG 65536                       // 128 x 66 words = 33792
#define SM_SQC 99328                       // 128 floats (sq + SQOFF)
#define SM_SQR 99840                       // 128 floats (sq + SQOFF)
#define SM_LST 100352                      // 256 x 6 u32 = 6144 (col merge only)
#define SM_TOTAL 106496

__global__ __launch_bounds__(256, 2)
void gemm_topk_kernel(float* __restrict__ out) {
    extern __shared__ char smem_[];
    char* sm = smem_;
    uint32_t sbase = smem_u32(sm);
    int tid = threadIdx.x;
    int b = blockIdx.x;

    // triangular decode: b -> (I <= J)
    int bi = (int)((sqrtf(8.0f * (float)b + 1.0f) - 1.0f) * 0.5f);
    while ((bi + 1) * (bi + 2) / 2 <= b) bi++;
    while (bi * (bi + 1) / 2 > b) bi--;
    int J = bi, I = b - bi * (bi + 1) / 2;
    bool diag = (I == J);

    if (tid < 128) ((float*)(sm + SM_SQC))[tid] = g_sq[J * 128 + tid] + SQOFF;
    else           ((float*)(sm + SM_SQR))[tid - 128] = g_sq[I * 128 + (tid - 128)] + SQOFF;

    // ---- async fills: A (and B unless diag), 2048 cp16 each ----
    {
        const char* a = (const char*)(g_fh + (size_t)(I * 128) * DIM);
        #pragma unroll
        for (int it = 0; it < 8; it++) {
            int idx = tid + it * 256;              // 0..2047
            int row = idx >> 4, ch = idx & 15;
            cp16(sbase + SM_A + swz(row, ch), a + (size_t)row * 256 + ch * 16);
        }
        if (!diag) {
            const char* bp = (const char*)(g_fh + (size_t)(J * 128) * DIM);
            #pragma unroll
            for (int it = 0; it < 8; it++) {
                int idx = tid + it * 256;
                int row = idx >> 4, ch = idx & 15;
                cp16(sbase + SM_B + swz(row, ch), bp + (size_t)row * 256 + ch * 16);
            }
        }
        CP_COMMIT();
    }

    // ---- zero-fill slice of out (full coverage across grid) ----
    {
        float4 z = make_float4(0.f, 0.f, 0.f, 0.f);
        #pragma unroll
        for (int i = 0; i < 8; i++) {
            size_t gi = ((size_t)b * 8 + i) * 256 + tid;
            if (gi < (size_t)4194304) ((float4*)out)[gi] = z;
        }
    }

    CP_WAIT0();
    __syncthreads();

    int wq = tid >> 5, l = tid & 31;
    int wm = wq & 3, wn = wq >> 2;            // 4x2 warps: 32-row x 32-col regions
    int lrow = (l & 7) | (((l >> 3) & 1) << 3);
    int kinc = (l >> 4) & 1;

    uint32_t Abase = sbase + SM_A;

    uint32_t nbA[6], nbB[6];                   // persistent row top-6 (ILP pair)
    #pragma unroll
    for (int k = 0; k < 6; k++) { nbA[k] = 0xFFFFFFFFu; nbB[k] = 0xFFFFFFFFu; }

    const float* sqc = (const float*)(sm + SM_SQC);
    const float* sqr = (const float*)(sm + SM_SQR);
    uint32_t* lists = (uint32_t*)(sm + SM_LST);

    #pragma unroll 1
    for (int h = 0; h < 2; h++) {
        uint32_t Bbase = (diag ? Abase : (sbase + SM_B)) + h * 16384;

        // ---- fp16 HMMA: single chain, 8 k16-steps, 128x64 half ----
        float acc[2][4][4];
        #pragma unroll
        for (int mi = 0; mi < 2; mi++)
            #pragma unroll
            for (int nf = 0; nf < 4; nf++)
                #pragma unroll
                for (int q = 0; q < 4; q++) acc[mi][nf][q] = 0.0f;

        #pragma unroll
        for (int ks = 0; ks < 8; ks++) {
            int ch = ks * 2 + kinc;
            uint32_t a[2][4];
            #pragma unroll
            for (int mi = 0; mi < 2; mi++)
                ldsm_x4(a[mi], Abase + swz(wm * 32 + mi * 16 + lrow, ch));
            uint32_t bb[2][4];
            #pragma unroll
            for (int ng = 0; ng < 2; ng++)
                ldsm_x4(bb[ng], Bbase + swz(wn * 32 + ng * 16 + lrow, ch));
            #pragma unroll
            for (int mi = 0; mi < 2; mi++)
                #pragma unroll
                for (int ng = 0; ng < 2; ng++) {
                    mma16816(acc[mi][ng * 2 + 0], a[mi], bb[ng][0], bb[ng][2]);
                    mma16816(acc[mi][ng * 2 + 1], a[mi], bb[ng][1], bb[ng][3]);
                }
        }

        // ---- stage v = (sq_col + OFF) - 2*dot  (> 0 always) ----
        // diag self-entry staged as exactly 0.0f -> minimal key, exact in merge
        #pragma unroll
        for (int mi = 0; mi < 2; mi++) {
            int r0 = wm * 32 + mi * 16 + (l >> 2);
            #pragma unroll
            for (int nf = 0; nf < 4; nf++) {
                int col = wn * 32 + nf * 8 + 2 * (l & 3);    // local 0..63
                int cf = h * 64 + col;                        // tile col 0..127
                float2 p0, p1;
                p0.x = sqc[cf]     - 2.0f * acc[mi][nf][0];
                p0.y = sqc[cf + 1] - 2.0f * acc[mi][nf][1];
                p1.x = sqc[cf]     - 2.0f * acc[mi][nf][2];
                p1.y = sqc[cf + 1] - 2.0f * acc[mi][nf][3];
                if (diag) {
                    if (r0 == cf)         p0.x = 0.0f;
                    if (r0 == cf + 1)     p0.y = 0.0f;
                    if (r0 + 8 == cf)     p1.x = 0.0f;
                    if (r0 + 8 == cf + 1) p1.y = 0.0f;
                }
                *(float2*)(sm + SM_STG + (r0 * 66 + col) * 4) = p0;
                *(float2*)(sm + SM_STG + ((r0 + 8) * 66 + col) * 4) = p1;
            }
        }
        __syncthreads();

        // ---- row scan into persistent ILP pair: 2 threads/row x 32 cols ----
        // indices are LOCAL tile columns (7 bits); slot J implies the block
        {
            int r = tid >> 1, sh = tid & 1;
            const char* srow = sm + SM_STG + (r * 66 + sh * 32) * 4;
            int cl = h * 64 + sh * 32;                 // local col base, 0..127
            #pragma unroll
            for (int i = 0; i < 16; i++) {
                float2 v = *(const float2*)(srow + i * 8);
                ins6u(packpos(v.x, cl + 2 * i), nbA);        // independent chains
                ins6u(packpos(v.y, cl + 2 * i + 1), nbB);
            }
        }

        // ---- col scan (skip on diagonal): 4 threads/col x 32 rows, ILP pair --
        // v' = staged - (sq_c+OFF) + (sq_r+OFF) = sq_r + OFF - 2*dot  (> 0)
        if (!diag) {
            int c = tid & 63, q = tid >> 6;
            float sjc = sqc[h * 64 + c];
            uint32_t cnA[6], cnB[6];
            #pragma unroll
            for (int k = 0; k < 6; k++) { cnA[k] = 0xFFFFFFFFu; cnB[k] = 0xFFFFFFFFu; }
            int rbase = q * 32;
            #pragma unroll
            for (int i = 0; i < 16; i++) {
                int r0 = rbase + 2 * i, r1 = r0 + 1;
                float s0 = *(const float*)(sm + SM_STG + (r0 * 66 + c) * 4);
                float s1 = *(const float*)(sm + SM_STG + (r1 * 66 + c) * 4);
                ins6u(packpos(s0 - sjc + sqr[r0], r0), cnA);
                ins6u(packpos(s1 - sjc + sqr[r1], r1), cnB);
            }
            #pragma unroll
            for (int k = 0; k < 6; k++) ins6u(cnB[k], cnA);
            #pragma unroll
            for (int k = 0; k < 6; k++) lists[tid * 6 + k] = cnA[k];
            __syncthreads();
            if (tid < 64) {
                uint32_t mb[6];
                #pragma unroll
                for (int k = 0; k < 6; k++) mb[k] = 0xFFFFFFFFu;
                #pragma unroll
                for (int s = 0; s < 4; s++) {
                    const uint32_t* L = lists + (s * 64 + tid) * 6;
                    #pragma unroll
                    for (int k = 0; k < 6; k++) ins6u(L[k], mb);
                }
                uint32_t* dst = g_top + ((size_t)(J * 128 + h * 64 + tid) * 64 + I) * 6;
                #pragma unroll
                for (int k = 0; k < 6; k++) dst[k] = mb[k];
            }
        }
        __syncthreads();   // STG/LST reuse in next half
    }

    // ---- final row merge: fold B list, then lane-pair shuffle ----
    {
        #pragma unroll
        for (int k = 0; k < 6; k++) ins6u(nbB[k], nbA);
        uint32_t tv[6];
        #pragma unroll
        for (int k = 0; k < 6; k++)
            tv[k] = __shfl_xor_sync(0xffffffffu, nbA[k], 1);
        #pragma unroll
        for (int k = 0; k < 6; k++) ins6u(tv[k], nbA);
        if ((tid & 1) == 0) {
            uint32_t* dst = g_top + ((size_t)(I * 128 + (tid >> 1)) * 64 + J) * 6;
            #pragma unroll
            for (int k = 0; k < 6; k++) dst[k] = nbA[k];
        }
    }
}

// ---------------- kernel 3: merge 64 slots (u64 keys), recompute, scatter -----
__global__ __launch_bounds__(256)
void merge_scatter_kernel(const float* __restrict__ f, float* __restrict__ out) {
    int warp = threadIdx.x >> 5, l = threadIdx.x & 31;
    int r = blockIdx.x * 8 + warp;

    // gather top-6 over 384 candidates; rebuild full index from slot position
    uint64_t nb[6];
    #pragma unroll
    for (int k = 0; k < 6; k++) nb[k] = ~0ull;
    const uint32_t* base = g_top + (size_t)r * 384;
    #pragma unroll
    for (int i = 0; i < 12; i++) {
        int e = l + 32 * i;                     // 0..383
        uint32_t k = base[e];
        uint32_t slot = (uint32_t)e / 6u;       // which partner block
        uint32_t fidx = slot * 128u + (k & 0x7Fu);
        uint64_t ku = ((uint64_t)(k & 0xFFFFFF80u) << 13) | fidx;
        ins6u64(ku, nb);
    }
    // butterfly merge: SNAPSHOT partner's full list BEFORE inserting
    #pragma unroll
    for (int off = 16; off; off >>= 1) {
        uint64_t tv[6];
        #pragma unroll
        for (int k = 0; k < 6; k++)
            tv[k] = __shfl_xor_sync(0xffffffffu, nb[k], off);
        #pragma unroll
        for (int k = 0; k < 6; k++) ins6u64(tv[k], nb);
    }
    #pragma unroll
    for (int k = 0; k < 6; k++) nb[k] = __shfl_sync(0xffffffffu, nb[k], 0);

    // exact fp32 dots for the 6 selected neighbors (warp-cooperative)
    float4 fr = ((const float4*)(f + (size_t)r * DIM))[l];
    float dots[6];
    #pragma unroll
    for (int k = 0; k < 6; k++) {
        int idx = (int)(nb[k] & 0x1FFFu);
        float4 fj = ((const float4*)(f + (size_t)idx * DIM))[l];
        float p = fr.x * fj.x + fr.y * fj.y + fr.z * fj.z + fr.w * fj.w;
        #pragma unroll
        for (int o = 16; o; o >>= 1) p += __shfl_xor_sync(0xffffffffu, p, o);
        dots[k] = p;
    }

    if (l == 0) {
        float sq_r = g_sq[r];
        float d[6];
        int idxs[6];
        #pragma unroll
        for (int k = 0; k < 6; k++) {
            int idx = (int)(nb[k] & 0x1FFFu);
            idxs[k] = idx;
            if (idx == r) {
                d[k] = 1e-15f;                   // matches forced d_self^2 = 0
            } else {
                float d2 = sq_r + g_sq[idx] - 2.0f * dots[k];
                d[k] = sqrtf(fmaxf(d2, 1e-30f));
            }
        }
        float thr = d[0];
        #pragma unroll
        for (int k = 1; k < 6; k++) thr = fmaxf(thr, d[k]);
        float wv[6]; float norm = 0.0f;
        #pragma unroll
        for (int k = 0; k < 6; k++) { wv[k] = thr - d[k] + 1e-10f; norm += wv[k]; }
        float inv = 1.0f / fmaxf(norm, 1e-12f);
        #pragma unroll
        for (int k = 0; k < 6; k++)
            out[(size_t)r * NPTS + idxs[k]] = wv[k] * inv;
    }
}

// ---------------- launch ------------------------------------------------------
extern "C" void kernel_launch(void* const* d_in, const int* in_sizes, int n_in,
                              void* d_out, int out_size) {
    const float* features = (const float*)d_in[0];
    float* out = (float*)d_out;
    (void)in_sizes; (void)n_in; (void)out_size;

    cudaFuncSetAttribute(gemm_topk_kernel,
                         cudaFuncAttributeMaxDynamicSharedMemorySize, SM_TOTAL);

    prep_kernel<<<NPTS / 8, 256>>>(features);
    gemm_topk_kernel<<<NTILES, 256, SM_TOTAL>>>(out);
    merge_scatter_kernel<<<NPTS / 8, 256>>>(features, out);
}

// round 17
// speedup vs baseline: 1.5636x; 1.5636x over previous
#include <cuda_runtime.h>
#include <cuda_fp16.h>
#include <cstdint>

#define NPTS 8192
#define DIM  128
#define NTILES 2080            // 64*65/2 triangle tiles, 128x128 each
#define SQOFF 256.0f           // positivity offset (> max row norm ~190)

// ---------------- scratch -----------------------------------------------------
static __device__ __half    g_fh[(size_t)NPTS * DIM];      // fp16 features
static __device__ float     g_sq[NPTS];                    // exact fp32 row norms
static __device__ uint32_t  g_top[(size_t)NPTS * 64 * 6];  // per-row 64 slot key lists

// ---------------- helpers ------------------------------------------------------
__device__ __forceinline__ uint32_t smem_u32(const void* p) {
    uint32_t a;
    asm("{ .reg .u64 t; cvta.to.shared.u64 t, %1; cvt.u32.u64 %0, t; }"
        : "=r"(a) : "l"(p));
    return a;
}
__device__ __forceinline__ void cp16(uint32_t dst, const void* src) {
    asm volatile("cp.async.cg.shared.global [%0], [%1], 16;"
                 :: "r"(dst), "l"(src) : "memory");
}
#define CP_COMMIT() asm volatile("cp.async.commit_group;" ::: "memory")
#define CP_WAIT0()  asm volatile("cp.async.wait_group 0;" ::: "memory")

__device__ __forceinline__ void ldsm_x4(uint32_t* r, uint32_t addr) {
    asm volatile("ldmatrix.sync.aligned.m8n8.x4.shared.b16 {%0,%1,%2,%3}, [%4];"
        : "=r"(r[0]), "=r"(r[1]), "=r"(r[2]), "=r"(r[3]) : "r"(addr));
}
__device__ __forceinline__ void mma16816(float* c, const uint32_t* a,
                                         uint32_t b0, uint32_t b1) {
    asm volatile("mma.sync.aligned.m16n8k16.row.col.f32.f16.f16.f32 "
        "{%0,%1,%2,%3}, {%4,%5,%6,%7}, {%8,%9}, {%0,%1,%2,%3};"
        : "+f"(c[0]), "+f"(c[1]), "+f"(c[2]), "+f"(c[3])
        : "r"(a[0]), "r"(a[1]), "r"(a[2]), "r"(a[3]), "r"(b0), "r"(b1));
}

// pack for POSITIVE floats with 7-bit LOCAL index: 25 value bits, single LOP3
__device__ __forceinline__ uint32_t packpos(float v, int idx) {
    return (__float_as_uint(v) & 0xFFFFFF80u) | (uint32_t)idx;
}

// swizzled byte offset inside a tile with 256B rows (16 chunks of 16B)
__device__ __forceinline__ uint32_t swz(int row, int chunk) {
    return (uint32_t)(row * 256 + (((chunk ^ row) & 7) | (chunk & 8)) * 16);
}

// top-6 insert on packed keys, ascending
__device__ __forceinline__ void ins6u(uint32_t k, uint32_t* nb) {
    if (k < nb[5]) {
        nb[5] = k;
        #pragma unroll
        for (int i = 5; i > 0; i--) {
            uint32_t lo = min(nb[i - 1], nb[i]);
            uint32_t hi = max(nb[i - 1], nb[i]);
            nb[i - 1] = lo; nb[i] = hi;
        }
    }
}
__device__ __forceinline__ void ins6u64(uint64_t k, uint64_t* nb) {
    if (k < nb[5]) {
        nb[5] = k;
        #pragma unroll
        for (int i = 5; i > 0; i--) {
            uint64_t lo = (nb[i] < nb[i - 1]) ? nb[i] : nb[i - 1];
            uint64_t hi = (nb[i] < nb[i - 1]) ? nb[i - 1] : nb[i];
            nb[i - 1] = lo; nb[i] = hi;
        }
    }
}

// ---------------- kernel 1: fp16 convert + exact row norms --------------------
__global__ __launch_bounds__(256) void prep_kernel(const float* __restrict__ f) {
    int wid = threadIdx.x >> 5, lane = threadIdx.x & 31;
    int row = blockIdx.x * 8 + wid;
    float4 v = ((const float4*)f)[row * 32 + lane];
    float s = v.x * v.x + v.y * v.y + v.z * v.z + v.w * v.w;
    __half2 h0 = __floats2half2_rn(v.x, v.y);
    __half2 h1 = __floats2half2_rn(v.z, v.w);
    uint2 u;
    u.x = *(uint32_t*)&h0; u.y = *(uint32_t*)&h1;
    *(uint2*)(g_fh + (size_t)row * DIM + lane * 4) = u;
    #pragma unroll
    for (int o = 16; o; o >>= 1) s += __shfl_xor_sync(0xffffffffu, s, o);
    if (lane == 0) g_sq[row] = s;
}

// ---------------- kernel 2: 128x128 symmetric tile, 2 col-half passes ---------
#define SM_A   0                           // 128 x 256 = 32768
#define SM_B   32768                       // 128 x 256 = 32768
#define SM_STG 65536                       // 128 x 66 words = 33792
#define SM_SQC 99328                       // 128 floats (sq + SQOFF)
#define SM_SQR 99840                       // 128 floats (sq + SQOFF)
#define SM_LST 100352                      // 256 x 6 u32 = 6144 (col merge only)
#define SM_TOTAL 106496

__global__ __launch_bounds__(256, 2)
void gemm_topk_kernel(float* __restrict__ out) {
    extern __shared__ char smem_[];
    char* sm = smem_;
    uint32_t sbase = smem_u32(sm);
    int tid = threadIdx.x;
    int b = blockIdx.x;

    // triangular decode: b -> (I <= J)
    int bi = (int)((sqrtf(8.0f * (float)b + 1.0f) - 1.0f) * 0.5f);
    while ((bi + 1) * (bi + 2) / 2 <= b) bi++;
    while (bi * (bi + 1) / 2 > b) bi--;
    int J = bi, I = b - bi * (bi + 1) / 2;
    bool diag = (I == J);

    if (tid < 128) ((float*)(sm + SM_SQC))[tid] = g_sq[J * 128 + tid] + SQOFF;
    else           ((float*)(sm + SM_SQR))[tid - 128] = g_sq[I * 128 + (tid - 128)] + SQOFF;

    // ---- async fills: A (and B unless diag), 2048 cp16 each ----
    {
        const char* a = (const char*)(g_fh + (size_t)(I * 128) * DIM);
        #pragma unroll
        for (int it = 0; it < 8; it++) {
            int idx = tid + it * 256;              // 0..2047
            int row = idx >> 4, ch = idx & 15;
            cp16(sbase + SM_A + swz(row, ch), a + (size_t)row * 256 + ch * 16);
        }
        if (!diag) {
            const char* bp = (const char*)(g_fh + (size_t)(J * 128) * DIM);
            #pragma unroll
            for (int it = 0; it < 8; it++) {
                int idx = tid + it * 256;
                int row = idx >> 4, ch = idx & 15;
                cp16(sbase + SM_B + swz(row, ch), bp + (size_t)row * 256 + ch * 16);
            }
        }
        CP_COMMIT();
    }

    // ---- zero-fill slice of out (full coverage across grid) ----
    {
        float4 z = make_float4(0.f, 0.f, 0.f, 0.f);
        #pragma unroll
        for (int i = 0; i < 8; i++) {
            size_t gi = ((size_t)b * 8 + i) * 256 + tid;
            if (gi < (size_t)4194304) ((float4*)out)[gi] = z;
        }
    }

    CP_WAIT0();
    __syncthreads();

    int wq = tid >> 5, l = tid & 31;
    int wm = wq & 3, wn = wq >> 2;            // 4x2 warps: 32-row x 32-col regions
    int lrow = (l & 7) | (((l >> 3) & 1) << 3);
    int kinc = (l >> 4) & 1;

    uint32_t Abase = sbase + SM_A;

    uint32_t nb6[6];                           // persistent row top-6 (2 thr/row)
    #pragma unroll
    for (int k = 0; k < 6; k++) nb6[k] = 0xFFFFFFFFu;

    const float* sqc = (const float*)(sm + SM_SQC);
    const float* sqr = (const float*)(sm + SM_SQR);
    uint32_t* lists = (uint32_t*)(sm + SM_LST);

    #pragma unroll 1
    for (int h = 0; h < 2; h++) {
        uint32_t Bbase = (diag ? Abase : (sbase + SM_B)) + h * 16384;

        // ---- fp16 HMMA: single chain, 8 k16-steps, 128x64 half ----
        float acc[2][4][4];
        #pragma unroll
        for (int mi = 0; mi < 2; mi++)
            #pragma unroll
            for (int nf = 0; nf < 4; nf++)
                #pragma unroll
                for (int q = 0; q < 4; q++) acc[mi][nf][q] = 0.0f;

        #pragma unroll
        for (int ks = 0; ks < 8; ks++) {
            int ch = ks * 2 + kinc;
            uint32_t a[2][4];
            #pragma unroll
            for (int mi = 0; mi < 2; mi++)
                ldsm_x4(a[mi], Abase + swz(wm * 32 + mi * 16 + lrow, ch));
            uint32_t bb[2][4];
            #pragma unroll
            for (int ng = 0; ng < 2; ng++)
                ldsm_x4(bb[ng], Bbase + swz(wn * 32 + ng * 16 + lrow, ch));
            #pragma unroll
            for (int mi = 0; mi < 2; mi++)
                #pragma unroll
                for (int ng = 0; ng < 2; ng++) {
                    mma16816(acc[mi][ng * 2 + 0], a[mi], bb[ng][0], bb[ng][2]);
                    mma16816(acc[mi][ng * 2 + 1], a[mi], bb[ng][1], bb[ng][3]);
                }
        }

        // ---- stage v = (sq_col + OFF) - 2*dot  (> 0 always) ----
        // diag self-entry staged as exactly 0.0f -> minimal key, exact in merge
        #pragma unroll
        for (int mi = 0; mi < 2; mi++) {
            int r0 = wm * 32 + mi * 16 + (l >> 2);
            #pragma unroll
            for (int nf = 0; nf < 4; nf++) {
                int col = wn * 32 + nf * 8 + 2 * (l & 3);    // local 0..63
                int cf = h * 64 + col;                        // tile col 0..127
                float2 p0, p1;
                p0.x = sqc[cf]     - 2.0f * acc[mi][nf][0];
                p0.y = sqc[cf + 1] - 2.0f * acc[mi][nf][1];
                p1.x = sqc[cf]     - 2.0f * acc[mi][nf][2];
                p1.y = sqc[cf + 1] - 2.0f * acc[mi][nf][3];
                if (diag) {
                    if (r0 == cf)         p0.x = 0.0f;
                    if (r0 == cf + 1)     p0.y = 0.0f;
                    if (r0 + 8 == cf)     p1.x = 0.0f;
                    if (r0 + 8 == cf + 1) p1.y = 0.0f;
                }
                *(float2*)(sm + SM_STG + (r0 * 66 + col) * 4) = p0;
                *(float2*)(sm + SM_STG + ((r0 + 8) * 66 + col) * 4) = p1;
            }
        }
        __syncthreads();

        // ---- row scan into persistent nb6: 2 threads/row x 32 cols ----
        // keys carry LOCAL tile column (7 bits); slot position implies block J
        {
            int r = tid >> 1, sh = tid & 1;
            const char* srow = sm + SM_STG + (r * 66 + sh * 32) * 4;
            int cl = h * 64 + sh * 32;                 // local col base, 0..127
            #pragma unroll
            for (int i = 0; i < 16; i++) {
                float2 v = *(const float2*)(srow + i * 8);
                ins6u(packpos(v.x, cl + 2 * i), nb6);
                ins6u(packpos(v.y, cl + 2 * i + 1), nb6);
            }
        }

        // ---- col scan (skip on diagonal): 4 threads/col x 32 rows ----
        // v' = staged - (sq_c+OFF) + (sq_r+OFF) = sq_r + OFF - 2*dot  (> 0)
        if (!diag) {
            int c = tid & 63, q = tid >> 6;
            float sjc = sqc[h * 64 + c];
            uint32_t cn[6];
            #pragma unroll
            for (int k = 0; k < 6; k++) cn[k] = 0xFFFFFFFFu;
            int rbase = q * 32;
            #pragma unroll
            for (int i = 0; i < 32; i++) {
                int rr = rbase + i;
                float sv = *(const float*)(sm + SM_STG + (rr * 66 + c) * 4);
                float v = sv - sjc + sqr[rr];
                ins6u(packpos(v, rr), cn);            // local row index (7 bits)
            }
            #pragma unroll
            for (int k = 0; k < 6; k++) lists[tid * 6 + k] = cn[k];
            __syncthreads();
            if (tid < 64) {
                uint32_t mb[6];
                #pragma unroll
                for (int k = 0; k < 6; k++) mb[k] = 0xFFFFFFFFu;
                #pragma unroll
                for (int s = 0; s < 4; s++) {
                    const uint32_t* L = lists + (s * 64 + tid) * 6;
                    #pragma unroll
                    for (int k = 0; k < 6; k++) ins6u(L[k], mb);
                }
                uint32_t* dst = g_top + ((size_t)(J * 128 + h * 64 + tid) * 64 + I) * 6;
                #pragma unroll
                for (int k = 0; k < 6; k++) dst[k] = mb[k];
            }
        }
        __syncthreads();   // STG/LST reuse in next half
    }

    // ---- final row merge: lane-pair shuffle (lanes 2t, 2t+1 adjacent) ----
    {
        uint32_t tv[6];
        #pragma unroll
        for (int k = 0; k < 6; k++)
            tv[k] = __shfl_xor_sync(0xffffffffu, nb6[k], 1);
        #pragma unroll
        for (int k = 0; k < 6; k++) ins6u(tv[k], nb6);
        if ((tid & 1) == 0) {
            uint32_t* dst = g_top + ((size_t)(I * 128 + (tid >> 1)) * 64 + J) * 6;
            #pragma unroll
            for (int k = 0; k < 6; k++) dst[k] = nb6[k];
        }
    }
}

// ---------------- kernel 3: merge 64 slots (u64 keys), recompute, scatter -----
__global__ __launch_bounds__(256)
void merge_scatter_kernel(const float* __restrict__ f, float* __restrict__ out) {
    int warp = threadIdx.x >> 5, l = threadIdx.x & 31;
    int r = blockIdx.x * 8 + warp;

    // gather top-6 over 384 candidates; rebuild full index from slot position
    uint64_t nb[6];
    #pragma unroll
    for (int k = 0; k < 6; k++) nb[k] = ~0ull;
    const uint32_t* base = g_top + (size_t)r * 384;
    #pragma unroll
    for (int i = 0; i < 12; i++) {
        int e = l + 32 * i;                     // 0..383
        uint32_t k = base[e];
        uint32_t slot = (uint32_t)e / 6u;       // which partner block
        uint32_t fidx = slot * 128u + (k & 0x7Fu);
        uint64_t ku = ((uint64_t)(k & 0xFFFFFF80u) << 13) | fidx;
        ins6u64(ku, nb);
    }
    // butterfly merge: SNAPSHOT partner's full list BEFORE inserting
    #pragma unroll
    for (int off = 16; off; off >>= 1) {
        uint64_t tv[6];
        #pragma unroll
        for (int k = 0; k < 6; k++)
            tv[k] = __shfl_xor_sync(0xffffffffu, nb[k], off);
        #pragma unroll
        for (int k = 0; k < 6; k++) ins6u64(tv[k], nb);
    }
    #pragma unroll
    for (int k = 0; k < 6; k++) nb[k] = __shfl_sync(0xffffffffu, nb[k], 0);

    // exact fp32 dots for the 6 selected neighbors (warp-cooperative)
    float4 fr = ((const float4*)(f + (size_t)r * DIM))[l];
    float dots[6];
    #pragma unroll
    for (int k = 0; k < 6; k++) {
        int idx = (int)(nb[k] & 0x1FFFu);
        float4 fj = ((const float4*)(f + (size_t)idx * DIM))[l];
        float p = fr.x * fj.x + fr.y * fj.y + fr.z * fj.z + fr.w * fj.w;
        #pragma unroll
        for (int o = 16; o; o >>= 1) p += __shfl_xor_sync(0xffffffffu, p, o);
        dots[k] = p;
    }

    if (l == 0) {
        float sq_r = g_sq[r];
        float d[6];
        int idxs[6];
        #pragma unroll
        for (int k = 0; k < 6; k++) {
            int idx = (int)(nb[k] & 0x1FFFu);
            idxs[k] = idx;
            if (idx == r) {
                d[k] = 1e-15f;                   // matches forced d_self^2 = 0
            } else {
                float d2 = sq_r + g_sq[idx] - 2.0f * dots[k];
                d[k] = sqrtf(fmaxf(d2, 1e-30f));
            }
        }
        float thr = d[0];
        #pragma unroll
        for (int k = 1; k < 6; k++) thr = fmaxf(thr, d[k]);
        float wv[6]; float norm = 0.0f;
        #pragma unroll
        for (int k = 0; k < 6; k++) { wv[k] = thr - d[k] + 1e-10f; norm += wv[k]; }
        float inv = 1.0f / fmaxf(norm, 1e-12f);
        #pragma unroll
        for (int k = 0; k < 6; k++)
            out[(size_t)r * NPTS + idxs[k]] = wv[k] * inv;
    }
}

// ---------------- launch ------------------------------------------------------
extern "C" void kernel_launch(void* const* d_in, const int* in_sizes, int n_in,
                              void* d_out, int out_size) {
    const float* features = (const float*)d_in[0];
    float* out = (float*)d_out;
    (void)in_sizes; (void)n_in; (void)out_size;

    cudaFuncSetAttribute(gemm_topk_kernel,
                         cudaFuncAttributeMaxDynamicSharedMemorySize, SM_TOTAL);

    prep_kernel<<<NPTS / 8, 256>>>(features);
    gemm_topk_kernel<<<NTILES, 256, SM_TOTAL>>>(out);
    merge_scatter_kernel<<<NPTS / 8, 256>>>(features, out);
}